// round 12
// baseline (speedup 1.0000x reference)
#include <cuda_runtime.h>
#include <cstdint>

#define N_SAMPLES 4194304
#define N_RAYS    65536
#define TPB       256

// Segment-start table: g_start[r] = index of first sample of ray r; g_start[N_RAYS] = N.
// __device__ global (static) — no dynamic allocation.
__device__ int g_start[N_RAYS + 1];

// ---------------------------------------------------------------------------
// Pass 1: find segment boundaries in the sorted ray_indices array.
// Each thread handles 4 samples via int4; each ray-start entry is written by
// exactly one thread (the one owning the first sample of that ray), so the
// pass is deterministic and atomic-free. Empty rays get start = next sample
// index (=> empty range in pass 2).
// ---------------------------------------------------------------------------
__global__ __launch_bounds__(TPB)
void boundary_kernel(const int4* __restrict__ idx4,
                     const int*  __restrict__ idx)
{
    const int t = blockIdx.x * blockDim.x + threadIdx.x;   // 0 .. N/4-1
    const int4 v = idx4[t];
    const int base = 4 * t;

    if (t == 0) {
        // leading (possibly empty) rays and the first ray start at 0
        for (int r = 0; r <= v.x; ++r) g_start[r] = 0;
    } else {
        const int prev = idx[base - 1];                    // L1/L2 hit (same line mostly)
        for (int r = prev + 1; r <= v.x; ++r) g_start[r] = base;
    }
    for (int r = v.x + 1; r <= v.y; ++r) g_start[r] = base + 1;
    for (int r = v.y + 1; r <= v.z; ++r) g_start[r] = base + 2;
    for (int r = v.z + 1; r <= v.w; ++r) g_start[r] = base + 3;

    if (t == (N_SAMPLES / 4) - 1) {
        for (int r = v.w + 1; r <= N_RAYS; ++r) g_start[r] = N_SAMPLES;
    }
}

// ---------------------------------------------------------------------------
// Pass 2: one warp per ray. Lanes stride the segment (2x unrolled for MLP),
// accumulate w*rgb in registers, warp shfl-reduce, lane 0 stores 3 floats.
// No atomics anywhere; output is fully written (no zero pass needed).
// ---------------------------------------------------------------------------
__global__ __launch_bounds__(TPB)
void gather_kernel(const float* __restrict__ rgb,    // [N*3]
                   const float* __restrict__ wts,    // [N]
                   float*       __restrict__ out)    // [N_RAYS*3]
{
    const int lane = threadIdx.x & 31;
    const int warp = threadIdx.x >> 5;
    const int ray  = blockIdx.x * (TPB / 32) + warp;

    const int s = g_start[ray];
    const int e = g_start[ray + 1];

    float ax = 0.f, ay = 0.f, az = 0.f;

    int i = s + lane;
    // 2x unrolled main loop: both i and i+32 valid
    while (i + 32 < e) {
        const float w0 = wts[i];
        const float w1 = wts[i + 32];
        const float r0 = rgb[3*i + 0], g0 = rgb[3*i + 1], b0 = rgb[3*i + 2];
        const float r1 = rgb[3*(i+32) + 0], g1 = rgb[3*(i+32) + 1], b1 = rgb[3*(i+32) + 2];
        ax = fmaf(w0, r0, ax); ay = fmaf(w0, g0, ay); az = fmaf(w0, b0, az);
        ax = fmaf(w1, r1, ax); ay = fmaf(w1, g1, ay); az = fmaf(w1, b1, az);
        i += 64;
    }
    while (i < e) {
        const float w = wts[i];
        ax = fmaf(w, rgb[3*i + 0], ax);
        ay = fmaf(w, rgb[3*i + 1], ay);
        az = fmaf(w, rgb[3*i + 2], az);
        i += 32;
    }

    // warp reduction (butterfly)
    #pragma unroll
    for (int m = 16; m > 0; m >>= 1) {
        ax += __shfl_xor_sync(0xFFFFFFFFu, ax, m);
        ay += __shfl_xor_sync(0xFFFFFFFFu, ay, m);
        az += __shfl_xor_sync(0xFFFFFFFFu, az, m);
    }

    if (lane == 0) {
        out[3 * ray + 0] = ax;
        out[3 * ray + 1] = ay;
        out[3 * ray + 2] = az;
    }
}

// ---------------------------------------------------------------------------
// Harness entry. Inputs (metadata order): rgb_samples[f32 N*3],
// weights_samples[f32 N], ray_indices[i32 N], n_rays[i32 scalar].
// Output: f32 [N_RAYS*3].
// ---------------------------------------------------------------------------
extern "C" void kernel_launch(void* const* d_in, const int* in_sizes, int n_in,
                              void* d_out, int out_size)
{
    const float* rgb  = (const float*)d_in[0];
    const float* wts  = (const float*)d_in[1];
    const int*   idx  = (const int*)d_in[2];
    float*       out  = (float*)d_out;

    // Pass 1: segment boundaries (1048576 threads)
    boundary_kernel<<<(N_SAMPLES / 4) / TPB, TPB>>>((const int4*)idx, idx);

    // Pass 2: per-ray gather (one warp per ray -> 65536 warps -> 8192 blocks)
    gather_kernel<<<N_RAYS / (TPB / 32), TPB>>>(rgb, wts, out);
}

// round 13
// speedup vs baseline: 2.1268x; 2.1268x over previous
#include <cuda_runtime.h>
#include <cstdint>

// Problem constants (fixed by the reference setup)
#define N_SAMPLES 4194304
#define N_RAYS    65536
#define SPT       8        // samples per thread (contiguous span)
#define TPB       256
#define FULLMASK  0xFFFFFFFFu

// ---------------------------------------------------------------------------
// Zero the output (harness poisons d_out to 0xAA before timing).
// ---------------------------------------------------------------------------
__global__ void zero_out_kernel(float4* __restrict__ out4, int n4) {
    int i = blockIdx.x * blockDim.x + threadIdx.x;
    if (i < n4) out4[i] = make_float4(0.f, 0.f, 0.f, 0.f);
}

// ---------------------------------------------------------------------------
// Sorted segment-sum, warp-aggregated:
//  1. Per-thread: front-batched vector loads, run-length accumulate; flush
//     INTERNAL run boundaries directly (rare: ~0.11/thread).
//  2. The leftover tail run of each lane enters a warp segmented scan
//     (head flag = tail run does not continue lane-1's tail). Only the
//     last lane of each warp-level segment performs the atomicAdd.
//  Net: ~4x fewer global atomics than per-thread flushing, identical loads.
// ---------------------------------------------------------------------------
__global__ __launch_bounds__(TPB)
void integrate_color_kernel(const float4* __restrict__ rgb4,   // [N*3/4]
                            const float4* __restrict__ w4,     // [N/4]
                            const int4*   __restrict__ idx4,   // [N/4]
                            float*        __restrict__ out)    // [N_RAYS*3]
{
    const int t    = blockIdx.x * blockDim.x + threadIdx.x;
    const int lane = threadIdx.x & 31;

    // ---- front-batched vector loads (max MLP) ----
    int4   iv[SPT / 4];            // 2 x int4
    float4 wv[SPT / 4];            // 2 x float4
    float4 cv[(SPT * 3) / 4];      // 6 x float4

    const long vb = (long)t * (SPT / 4);
    #pragma unroll
    for (int i = 0; i < SPT / 4; ++i) {
        iv[i] = idx4[vb + i];
        wv[i] = w4[vb + i];
    }
    const long cb = (long)t * ((SPT * 3) / 4);
    #pragma unroll
    for (int i = 0; i < (SPT * 3) / 4; ++i) {
        cv[i] = rgb4[cb + i];
    }

    // ---- unpack into flat register arrays ----
    int   ridx[SPT];
    float wgt[SPT];
    float col[SPT * 3];
    #pragma unroll
    for (int i = 0; i < SPT / 4; ++i) {
        ridx[4*i + 0] = iv[i].x; ridx[4*i + 1] = iv[i].y;
        ridx[4*i + 2] = iv[i].z; ridx[4*i + 3] = iv[i].w;
        wgt[4*i + 0] = wv[i].x;  wgt[4*i + 1] = wv[i].y;
        wgt[4*i + 2] = wv[i].z;  wgt[4*i + 3] = wv[i].w;
    }
    #pragma unroll
    for (int i = 0; i < (SPT * 3) / 4; ++i) {
        col[4*i + 0] = cv[i].x; col[4*i + 1] = cv[i].y;
        col[4*i + 2] = cv[i].z; col[4*i + 3] = cv[i].w;
    }

    // ---- per-thread run-length accumulate; flush internal boundaries ----
    const int f = ridx[0];            // first ray of this thread
    const int l = ridx[SPT - 1];      // last ray of this thread
    float ax = 0.f, ay = 0.f, az = 0.f;
    int cur = f;

    #pragma unroll
    for (int i = 0; i < SPT; ++i) {
        const int r = ridx[i];
        if (r != cur) {
            atomicAdd(&out[3 * cur + 0], ax);
            atomicAdd(&out[3 * cur + 1], ay);
            atomicAdd(&out[3 * cur + 2], az);
            cur = r;
            ax = ay = az = 0.f;
        }
        const float w = wgt[i];
        ax = fmaf(w, col[3*i + 0], ax);
        ay = fmaf(w, col[3*i + 1], ay);
        az = fmaf(w, col[3*i + 2], az);
    }
    // leftover: tail run of ray `l` with sum (ax,ay,az)

    // ---- warp segmented scan over tail sums ----
    // head flag: my tail value starts a new scan segment if
    //  - lane 0, or
    //  - my thread had an internal boundary (tail run began inside me), or
    //  - previous lane's last ray differs from my first ray.
    const int prev_l = __shfl_up_sync(FULLMASK, l, 1);
    unsigned headflag = (lane == 0) || (f != l) || (f != prev_l);
    const unsigned headflag0 = headflag;

    #pragma unroll
    for (int d = 1; d < 32; d <<= 1) {
        const float    ox = __shfl_up_sync(FULLMASK, ax, d);
        const float    oy = __shfl_up_sync(FULLMASK, ay, d);
        const float    oz = __shfl_up_sync(FULLMASK, az, d);
        const unsigned og = __shfl_up_sync(FULLMASK, headflag, d);
        if (lane >= d) {
            if (!headflag) { ax += ox; ay += oy; az += oz; }
            headflag |= og;
        }
    }

    // segment-last lanes flush the aggregated sum
    const unsigned next_head = __shfl_down_sync(FULLMASK, headflag0, 1);
    if (lane == 31 || next_head) {
        atomicAdd(&out[3 * l + 0], ax);
        atomicAdd(&out[3 * l + 1], ay);
        atomicAdd(&out[3 * l + 2], az);
    }
}

// ---------------------------------------------------------------------------
// Harness entry. Inputs (metadata order): rgb_samples[f32 N*3],
// weights_samples[f32 N], ray_indices[i32 N], n_rays[i32 scalar].
// Output: f32 [N_RAYS*3].
// ---------------------------------------------------------------------------
extern "C" void kernel_launch(void* const* d_in, const int* in_sizes, int n_in,
                              void* d_out, int out_size)
{
    const float4* rgb4 = (const float4*)d_in[0];
    const float4* w4   = (const float4*)d_in[1];
    const int4*   idx4 = (const int4*)d_in[2];
    float*        out  = (float*)d_out;

    // zero the output: N_RAYS*3 = 196608 floats = 49152 float4
    const int n4 = (N_RAYS * 3) / 4;
    zero_out_kernel<<<(n4 + TPB - 1) / TPB, TPB>>>((float4*)d_out, n4);

    // scatter-accumulate: 4194304 / 8 = 524288 threads
    const int n_threads = N_SAMPLES / SPT;
    integrate_color_kernel<<<n_threads / TPB, TPB>>>(rgb4, w4, idx4, out);
}